// round 4
// baseline (speedup 1.0000x reference)
#include <cuda_runtime.h>
#include <cuda_bf16.h>
#include <cstdint>

// out = RowLocalAttn(v@Wq, v@Wk, v@Wv) @ Wp + bp
// v: [65536, 256] fp32. GEMMs: warp mma.sync bf16, 3-pass hi/lo split, fp32 accum.
// R4: merged QKV GEMM (N=768), 3-stage cp.async pipeline, attention fused into
// the final GEMM prologue (x never hits global memory).

#define M_TOTAL 65536
#define DIM     256

// ---------------- scratch ----------------------------------------------------
__device__ __align__(128) unsigned short g_vhi[(size_t)M_TOTAL * DIM];
__device__ __align__(128) unsigned short g_vlo[(size_t)M_TOTAL * DIM];
__device__ __align__(128) float          g_qkv[(size_t)M_TOTAL * 3 * DIM]; // [M][768]
__device__ __align__(128) unsigned short g_wqkv[2 * 768 * 256];  // hi plane, lo plane ([n][k])
__device__ __align__(128) unsigned short g_wp[2 * 256 * 256];

// ---------------- PTX helpers ------------------------------------------------
__device__ __forceinline__ uint32_t smem_u32(const void* p) {
    uint32_t a;
    asm("{ .reg .u64 t; cvta.to.shared.u64 t, %1; cvt.u32.u64 %0, t; }" : "=r"(a) : "l"(p));
    return a;
}
__device__ __forceinline__ void cp_async16(uint32_t s, const void* g) {
    asm volatile("cp.async.cg.shared.global [%0], [%1], 16;" :: "r"(s), "l"(g));
}
__device__ __forceinline__ void cp_commit() { asm volatile("cp.async.commit_group;"); }
template<int N>
__device__ __forceinline__ void cp_wait() { asm volatile("cp.async.wait_group %0;" :: "n"(N)); }
__device__ __forceinline__ void ldsm4(uint32_t* r, uint32_t a) {
    asm volatile("ldmatrix.sync.aligned.m8n8.x4.shared.b16 {%0,%1,%2,%3}, [%4];"
        : "=r"(r[0]), "=r"(r[1]), "=r"(r[2]), "=r"(r[3]) : "r"(a));
}
__device__ __forceinline__ void mma16816(float* d, const uint32_t* a, const uint32_t* b) {
    asm volatile("mma.sync.aligned.m16n8k16.row.col.f32.bf16.bf16.f32 "
        "{%0,%1,%2,%3}, {%4,%5,%6,%7}, {%8,%9}, {%0,%1,%2,%3};"
        : "+f"(d[0]), "+f"(d[1]), "+f"(d[2]), "+f"(d[3])
        : "r"(a[0]), "r"(a[1]), "r"(a[2]), "r"(a[3]), "r"(b[0]), "r"(b[1]));
}
// swizzled offset in an N-row x 64-byte tile (16B granules)
__device__ __forceinline__ uint32_t swz(int row, int c) {
    return (uint32_t)(row * 64 + ((c ^ ((row >> 1) & 3)) << 4));
}

// ---------------- conversion kernels ----------------------------------------
__global__ __launch_bounds__(256)
void split_kernel(const float4* __restrict__ in, uint2* __restrict__ hi,
                  uint2* __restrict__ lo, int n4)
{
    int i = blockIdx.x * blockDim.x + threadIdx.x;
    if (i >= n4) return;
    float4 f = in[i];
    __nv_bfloat16 h0 = __float2bfloat16(f.x);
    __nv_bfloat16 h1 = __float2bfloat16(f.y);
    __nv_bfloat16 h2 = __float2bfloat16(f.z);
    __nv_bfloat16 h3 = __float2bfloat16(f.w);
    __nv_bfloat16 l0 = __float2bfloat16(f.x - __bfloat162float(h0));
    __nv_bfloat16 l1 = __float2bfloat16(f.y - __bfloat162float(h1));
    __nv_bfloat16 l2 = __float2bfloat16(f.z - __bfloat162float(h2));
    __nv_bfloat16 l3 = __float2bfloat16(f.w - __bfloat162float(h3));
    __nv_bfloat162 hp0 = __nv_bfloat162(h0, h1), hp1 = __nv_bfloat162(h2, h3);
    __nv_bfloat162 lp0 = __nv_bfloat162(l0, l1), lp1 = __nv_bfloat162(l2, l3);
    uint2 ho, lo2;
    ho.x = *(uint32_t*)&hp0; ho.y = *(uint32_t*)&hp1;
    lo2.x = *(uint32_t*)&lp0; lo2.y = *(uint32_t*)&lp1;
    hi[i] = ho; lo[i] = lo2;
}

__global__ __launch_bounds__(256)
void wconv_kernel(const float* __restrict__ Wq, const float* __restrict__ Wk,
                  const float* __restrict__ Wv, const float* __restrict__ Wp,
                  unsigned short* __restrict__ wqkv, unsigned short* __restrict__ wp)
{
    int wi = blockIdx.y;
    int n  = blockIdx.x;
    int k  = threadIdx.x;
    const float* W = (wi == 0) ? Wq : (wi == 1) ? Wk : (wi == 2) ? Wv : Wp;
    float val = W[k * 256 + n];
    __nv_bfloat16 h = __float2bfloat16(val);
    __nv_bfloat16 l = __float2bfloat16(val - __bfloat162float(h));
    if (wi < 3) {
        wqkv[(size_t)(wi * 256 + n) * 256 + k]                  = *(unsigned short*)&h;
        wqkv[(size_t)768 * 256 + (size_t)(wi * 256 + n) * 256 + k] = *(unsigned short*)&l;
    } else {
        wp[(size_t)n * 256 + k]                    = *(unsigned short*)&h;
        wp[(size_t)256 * 256 + (size_t)n * 256 + k] = *(unsigned short*)&l;
    }
}

// ---------------- QKV GEMM: 3-stage pipeline --------------------------------
// C[by*128..+128][bx*128..+128] = A @ B^T. A hi/lo [M][256], B hi/lo [Ntot][256].
static constexpr int STAGE_BYTES = 32768;
static constexpr int OFF_AH = 0, OFF_AL = 8192, OFF_BH = 16384, OFF_BL = 24576;
static constexpr int GEMM_SMEM = 3 * STAGE_BYTES;

__global__ __launch_bounds__(256)
void gemm3_kernel(const unsigned short* __restrict__ Ahi, const unsigned short* __restrict__ Alo,
                  const unsigned short* __restrict__ Bhi, const unsigned short* __restrict__ Blo,
                  float* __restrict__ C, int ldc)
{
    extern __shared__ char smem[];
    const uint32_t sb = smem_u32(smem);
    const int tid  = threadIdx.x;
    const int wid  = tid >> 5;
    const int lane = tid & 31;
    const int mw = wid & 1;        // 2 warp rows (64 each)
    const int nw = wid >> 1;       // 4 warp cols (32 each)

    const int mbase = blockIdx.y * 128;
    const int nbase = blockIdx.x * 128;

    auto load_chunk = [&](int kc, int s) {
        const uint32_t stg = sb + s * STAGE_BYTES;
        #pragma unroll
        for (int i = 0; i < 2; i++) {
            int u = tid + i * 256;             // 512 16B-units per 8K tile
            int row = u >> 2, c = u & 3;
            uint32_t so = swz(row, c);
            size_t ga = (size_t)(mbase + row) * 256 + kc * 32 + c * 8;
            size_t gb = (size_t)(nbase + row) * 256 + kc * 32 + c * 8;
            cp_async16(stg + OFF_AH + so, Ahi + ga);
            cp_async16(stg + OFF_AL + so, Alo + ga);
            cp_async16(stg + OFF_BH + so, Bhi + gb);
            cp_async16(stg + OFF_BL + so, Blo + gb);
        }
        cp_commit();
    };

    float acc[4][4][4];
    #pragma unroll
    for (int i = 0; i < 4; i++)
        #pragma unroll
        for (int j = 0; j < 4; j++)
            #pragma unroll
            for (int r = 0; r < 4; r++) acc[i][j][r] = 0.0f;

    load_chunk(0, 0);
    load_chunk(1, 1);

    for (int kc = 0; kc < 8; kc++) {
        if (kc == 7) cp_wait<0>(); else cp_wait<1>();
        __syncthreads();
        if (kc < 6) load_chunk(kc + 2, (kc + 2) % 3);

        const uint32_t stg = sb + (kc % 3) * STAGE_BYTES;
        #pragma unroll
        for (int ks = 0; ks < 2; ks++) {
            uint32_t a_hi[4][4], a_lo[4][4];
            {
                int arow = mw * 64 + (lane & 15);
                int ac   = ks * 2 + (lane >> 4);
                uint32_t base_off = swz(arow, ac);
                #pragma unroll
                for (int mt = 0; mt < 4; mt++) {
                    uint32_t off = base_off + mt * 16 * 64;
                    ldsm4(a_hi[mt], stg + OFF_AH + off);
                    ldsm4(a_lo[mt], stg + OFF_AL + off);
                }
            }
            uint32_t b_hi[4][2], b_lo[4][2];
            {
                int nr0 = nw * 32 + ((lane >> 4) << 3) + (lane & 7);
                int bc  = ks * 2 + ((lane >> 3) & 1);
                #pragma unroll
                for (int nh = 0; nh < 2; nh++) {
                    uint32_t off = swz(nr0 + nh * 16, bc);
                    uint32_t r[4];
                    ldsm4(r, stg + OFF_BH + off);
                    b_hi[nh * 2][0] = r[0]; b_hi[nh * 2][1] = r[1];
                    b_hi[nh * 2 + 1][0] = r[2]; b_hi[nh * 2 + 1][1] = r[3];
                    ldsm4(r, stg + OFF_BL + off);
                    b_lo[nh * 2][0] = r[0]; b_lo[nh * 2][1] = r[1];
                    b_lo[nh * 2 + 1][0] = r[2]; b_lo[nh * 2 + 1][1] = r[3];
                }
            }
            #pragma unroll
            for (int mt = 0; mt < 4; mt++)
                #pragma unroll
                for (int nt = 0; nt < 4; nt++) {
                    mma16816(acc[mt][nt], a_hi[mt], b_hi[nt]);
                    mma16816(acc[mt][nt], a_hi[mt], b_lo[nt]);
                    mma16816(acc[mt][nt], a_lo[mt], b_hi[nt]);
                }
        }
    }

    #pragma unroll
    for (int mt = 0; mt < 4; mt++) {
        int r0 = mbase + mw * 64 + mt * 16 + (lane >> 2);
        #pragma unroll
        for (int nt = 0; nt < 4; nt++) {
            int col = nbase + nw * 32 + nt * 8 + (lane & 3) * 2;
            *(float2*)(C + (size_t)r0 * ldc + col) = make_float2(acc[mt][nt][0], acc[mt][nt][1]);
            *(float2*)(C + (size_t)(r0 + 8) * ldc + col) = make_float2(acc[mt][nt][2], acc[mt][nt][3]);
        }
    }
}

// ---------------- fused attention + output GEMM ------------------------------
// Grid 512 CTAs x 512 threads. CTA owns 128 rows, full N=256.
// Prologue: 4 groups of 32 rows: load qkv fp32 -> smem, row-local attention,
// write x hi/lo (split bf16, swizzled) into resident A smem region.
// Mainloop: stream Wp hi/lo 32-k chunks (3-stage), warp tile 32x64.
static constexpr int XH_OFF   = 0;               // 8 chunks x 8KB
static constexpr int XL_OFF   = 65536;
static constexpr int QBUF_OFF = 131072;          // 32 rows x 772 floats
static constexpr int QSTR     = 772;
static constexpr int FB_STAGE = 32768;           // BH 16K | BL 16K  (overlaps QBUF)
static constexpr int FOFF_BH = 0, FOFF_BL = 16384;
static constexpr int SMEMF = QBUF_OFF + 32 * QSTR * 4;   // 229888

__global__ __launch_bounds__(512, 1)
void attn_gemm_kernel(const float* __restrict__ qkv,
                      const unsigned short* __restrict__ Bhi, const unsigned short* __restrict__ Blo,
                      const float* __restrict__ bias, float* __restrict__ C)
{
    extern __shared__ char smem[];
    const uint32_t sb = smem_u32(smem);
    float* qb = (float*)(smem + QBUF_OFF);
    const int tid  = threadIdx.x;
    const int wid  = tid >> 5;
    const int lane = tid & 31;
    const int m0 = blockIdx.x * 128;

    // ---------- prologue: attention over 4 groups of 32 rows ----------
    const float scale = 0.17677669529663687f;  // 1/sqrt(32)
    for (int rg = 0; rg < 4; rg++) {
        // load qkv[32 rows][768] fp32 (stride QSTR in smem)
        const float4* src = (const float4*)(qkv + (size_t)(m0 + rg * 32) * 768);
        #pragma unroll
        for (int i = 0; i < 12; i++) {
            int u = tid + i * 512;          // 6144 float4
            int r = u / 192, c4 = u % 192;
            *((float4*)qb + r * 193 + c4) = src[r * 192 + c4];
        }
        __syncthreads();

        if (tid < 256) {
            const int r = tid >> 3;
            const int h = tid & 7;
            const float* q  = qb + r * QSTR + h * 32;
            const float* k  = qb + r * QSTR + 256;
            const float* vv = qb + r * QSTR + 512;

            float p[8];
            #pragma unroll
            for (int g = 0; g < 8; g++) p[g] = 0.0f;
            #pragma unroll
            for (int dd = 0; dd < 32; dd++) {
                int d = (dd + h * 4) & 31;    // bank-rotate
                float qd = q[d];
                #pragma unroll
                for (int g = 0; g < 8; g++)
                    p[g] = fmaf(qd, k[g * 32 + d], p[g]);
            }
            float mx = p[0] * scale;
            #pragma unroll
            for (int g = 1; g < 8; g++) mx = fmaxf(mx, p[g] * scale);
            float sum = 0.0f;
            #pragma unroll
            for (int g = 0; g < 8; g++) { p[g] = __expf(p[g] * scale - mx); sum += p[g]; }
            const float inv = 1.0f / sum;
            #pragma unroll
            for (int g = 0; g < 8; g++) p[g] *= inv;

            float o[32];
            #pragma unroll
            for (int dd = 0; dd < 32; dd++) {
                int d = (dd + h * 4) & 31;
                float a = 0.0f;
                #pragma unroll
                for (int g = 0; g < 8; g++)
                    a = fmaf(p[g], vv[g * 32 + d], a);
                o[d] = a;
            }

            unsigned short hbuf[32], lbuf[32];
            #pragma unroll
            for (int d = 0; d < 32; d++) {
                __nv_bfloat16 hb = __float2bfloat16(o[d]);
                __nv_bfloat16 lb = __float2bfloat16(o[d] - __bfloat162float(hb));
                hbuf[d] = *(unsigned short*)&hb;
                lbuf[d] = *(unsigned short*)&lb;
            }
            // X region: chunk = head h, row rr, 4 granules of 16B
            int rr = rg * 32 + r;
            #pragma unroll
            for (int gg = 0; gg < 4; gg++) {
                uint32_t off = h * 8192 + swz(rr, gg);
                *(uint4*)(smem + XH_OFF + off) = *(uint4*)(hbuf + gg * 8);
                *(uint4*)(smem + XL_OFF + off) = *(uint4*)(lbuf + gg * 8);
            }
        }
        __syncthreads();
    }

    // ---------- mainloop: stream Wp chunks ----------
    auto load_b = [&](int kc, int s) {
        const uint32_t stg = sb + QBUF_OFF + s * FB_STAGE;
        #pragma unroll
        for (int i = 0; i < 2; i++) {
            int u = tid + i * 512;           // 1024 granules per 16K tile
            int row = u >> 2, c = u & 3;
            uint32_t so = swz(row, c);
            size_t gb = (size_t)row * 256 + kc * 32 + c * 8;
            cp_async16(stg + FOFF_BH + so, Bhi + gb);
            cp_async16(stg + FOFF_BL + so, Blo + gb);
        }
        cp_commit();
    };

    const int mw = wid & 3;       // 4 warp rows (32 each)
    const int nw = wid >> 2;      // 4 warp cols (64 each)

    float acc[2][8][4];
    #pragma unroll
    for (int i = 0; i < 2; i++)
        #pragma unroll
        for (int j = 0; j < 8; j++)
            #pragma unroll
            for (int r = 0; r < 4; r++) acc[i][j][r] = 0.0f;

    load_b(0, 0);
    load_b(1, 1);

    for (int kc = 0; kc < 8; kc++) {
        if (kc == 7) cp_wait<0>(); else cp_wait<1>();
        __syncthreads();
        if (kc < 6) load_b(kc + 2, (kc + 2) % 3);

        const uint32_t bstg = sb + QBUF_OFF + (kc % 3) * FB_STAGE;
        #pragma unroll
        for (int ks = 0; ks < 2; ks++) {
            uint32_t a_hi[2][4], a_lo[2][4];
            {
                int arow = mw * 32 + (lane & 15);
                int ac   = ks * 2 + (lane >> 4);
                #pragma unroll
                for (int mt = 0; mt < 2; mt++) {
                    uint32_t off = (uint32_t)kc * 8192 + swz(arow + mt * 16, ac);
                    ldsm4(a_hi[mt], sb + XH_OFF + off);
                    ldsm4(a_lo[mt], sb + XL_OFF + off);
                }
            }
            uint32_t b_hi[8][2], b_lo[8][2];
            {
                int nr0 = nw * 64 + ((lane >> 4) << 3) + (lane & 7);
                int bc  = ks * 2 + ((lane >> 3) & 1);
                #pragma unroll
                for (int nh = 0; nh < 4; nh++) {
                    uint32_t off = swz(nr0 + nh * 16, bc);
                    uint32_t r[4];
                    ldsm4(r, bstg + FOFF_BH + off);
                    b_hi[nh * 2][0] = r[0]; b_hi[nh * 2][1] = r[1];
                    b_hi[nh * 2 + 1][0] = r[2]; b_hi[nh * 2 + 1][1] = r[3];
                    ldsm4(r, bstg + FOFF_BL + off);
                    b_lo[nh * 2][0] = r[0]; b_lo[nh * 2][1] = r[1];
                    b_lo[nh * 2 + 1][0] = r[2]; b_lo[nh * 2 + 1][1] = r[3];
                }
            }
            #pragma unroll
            for (int mt = 0; mt < 2; mt++)
                #pragma unroll
                for (int nt = 0; nt < 8; nt++) {
                    mma16816(acc[mt][nt], a_hi[mt], b_hi[nt]);
                    mma16816(acc[mt][nt], a_hi[mt], b_lo[nt]);
                    mma16816(acc[mt][nt], a_lo[mt], b_hi[nt]);
                }
        }
    }

    #pragma unroll
    for (int mt = 0; mt < 2; mt++) {
        int r0 = m0 + mw * 32 + mt * 16 + (lane >> 2);
        #pragma unroll
        for (int nt = 0; nt < 8; nt++) {
            int col = nw * 64 + nt * 8 + (lane & 3) * 2;
            float b0 = bias[col], b1 = bias[col + 1];
            *(float2*)(C + (size_t)r0 * 256 + col) =
                make_float2(acc[mt][nt][0] + b0, acc[mt][nt][1] + b1);
            *(float2*)(C + (size_t)(r0 + 8) * 256 + col) =
                make_float2(acc[mt][nt][2] + b0, acc[mt][nt][3] + b1);
        }
    }
}

// ---------------- launch ------------------------------------------------------
extern "C" void kernel_launch(void* const* d_in, const int* in_sizes, int n_in,
                              void* d_out, int out_size)
{
    const float* v  = (const float*)d_in[0];
    const float* Wq = (const float*)d_in[1];
    const float* Wk = (const float*)d_in[2];
    const float* Wv = (const float*)d_in[3];
    const float* Wp = (const float*)d_in[4];
    const float* bp = (const float*)d_in[5];
    float* out = (float*)d_out;

    unsigned short *vhi, *vlo, *wqkv, *wp;
    float *qkv;
    cudaGetSymbolAddress((void**)&vhi,  g_vhi);
    cudaGetSymbolAddress((void**)&vlo,  g_vlo);
    cudaGetSymbolAddress((void**)&wqkv, g_wqkv);
    cudaGetSymbolAddress((void**)&wp,   g_wp);
    cudaGetSymbolAddress((void**)&qkv,  g_qkv);

    cudaFuncSetAttribute(gemm3_kernel, cudaFuncAttributeMaxDynamicSharedMemorySize, GEMM_SMEM);
    cudaFuncSetAttribute(attn_gemm_kernel, cudaFuncAttributeMaxDynamicSharedMemorySize, SMEMF);

    int n4 = M_TOTAL * DIM / 4;
    split_kernel<<<(n4 + 255) / 256, 256>>>((const float4*)v, (uint2*)vhi, (uint2*)vlo, n4);
    wconv_kernel<<<dim3(256, 4), 256>>>(Wq, Wk, Wv, Wp, wqkv, wp);

    // fused QKV projection: N = 768
    dim3 gq(6, M_TOTAL / 128);
    gemm3_kernel<<<gq, 256, GEMM_SMEM>>>(vhi, vlo, wqkv, wqkv + 768 * 256, qkv, 768);

    // fused attention + output projection
    attn_gemm_kernel<<<M_TOTAL / 128, 512, SMEMF>>>(qkv, wp, wp + 256 * 256, bp, out);
}

// round 5
// speedup vs baseline: 1.2424x; 1.2424x over previous
#include <cuda_runtime.h>
#include <cuda_bf16.h>
#include <cstdint>

// out = RowLocalAttn(v@Wq, v@Wk, v@Wv) @ Wp + bp
// v: [65536, 256] fp32. GEMMs: warp mma.sync bf16, 3-pass hi/lo split, fp32 accum.
// R5: R3 structure + merged QKV GEMM (N=768), MMA pass-reorder (indep accums),
// conflict-free attention smem (pad 772 + rotation).

#define M_TOTAL 65536
#define DIM     256

// ---------------- scratch ----------------------------------------------------
__device__ __align__(128) unsigned short g_vhi[(size_t)M_TOTAL * DIM];
__device__ __align__(128) unsigned short g_vlo[(size_t)M_TOTAL * DIM];
__device__ __align__(128) float          g_qkv[(size_t)M_TOTAL * 3 * DIM]; // [M][768]
__device__ __align__(128) unsigned short g_xhi[(size_t)M_TOTAL * DIM];
__device__ __align__(128) unsigned short g_xlo[(size_t)M_TOTAL * DIM];
__device__ __align__(128) unsigned short g_wqkv[2 * 768 * 256];  // hi plane, lo plane ([n][k])
__device__ __align__(128) unsigned short g_wp[2 * 256 * 256];

// ---------------- PTX helpers ------------------------------------------------
__device__ __forceinline__ uint32_t smem_u32(const void* p) {
    uint32_t a;
    asm("{ .reg .u64 t; cvta.to.shared.u64 t, %1; cvt.u32.u64 %0, t; }" : "=r"(a) : "l"(p));
    return a;
}
__device__ __forceinline__ void cp_async16(uint32_t s, const void* g) {
    asm volatile("cp.async.cg.shared.global [%0], [%1], 16;" :: "r"(s), "l"(g));
}
__device__ __forceinline__ void cp_commit() { asm volatile("cp.async.commit_group;"); }
template<int N>
__device__ __forceinline__ void cp_wait() { asm volatile("cp.async.wait_group %0;" :: "n"(N)); }
__device__ __forceinline__ void ldsm4(uint32_t* r, uint32_t a) {
    asm volatile("ldmatrix.sync.aligned.m8n8.x4.shared.b16 {%0,%1,%2,%3}, [%4];"
        : "=r"(r[0]), "=r"(r[1]), "=r"(r[2]), "=r"(r[3]) : "r"(a));
}
__device__ __forceinline__ void mma16816(float* d, const uint32_t* a, const uint32_t* b) {
    asm volatile("mma.sync.aligned.m16n8k16.row.col.f32.bf16.bf16.f32 "
        "{%0,%1,%2,%3}, {%4,%5,%6,%7}, {%8,%9}, {%0,%1,%2,%3};"
        : "+f"(d[0]), "+f"(d[1]), "+f"(d[2]), "+f"(d[3])
        : "r"(a[0]), "r"(a[1]), "r"(a[2]), "r"(a[3]), "r"(b[0]), "r"(b[1]));
}
// swizzled offset in an N-row x 64-byte tile (16B granules)
__device__ __forceinline__ uint32_t swz(int row, int c) {
    return (uint32_t)(row * 64 + ((c ^ ((row >> 1) & 3)) << 4));
}

// ---------------- conversion kernels ----------------------------------------
__global__ __launch_bounds__(256)
void split_kernel(const float4* __restrict__ in, uint2* __restrict__ hi,
                  uint2* __restrict__ lo, int n4)
{
    int i = blockIdx.x * blockDim.x + threadIdx.x;
    if (i >= n4) return;
    float4 f = in[i];
    __nv_bfloat16 h0 = __float2bfloat16(f.x);
    __nv_bfloat16 h1 = __float2bfloat16(f.y);
    __nv_bfloat16 h2 = __float2bfloat16(f.z);
    __nv_bfloat16 h3 = __float2bfloat16(f.w);
    __nv_bfloat16 l0 = __float2bfloat16(f.x - __bfloat162float(h0));
    __nv_bfloat16 l1 = __float2bfloat16(f.y - __bfloat162float(h1));
    __nv_bfloat16 l2 = __float2bfloat16(f.z - __bfloat162float(h2));
    __nv_bfloat16 l3 = __float2bfloat16(f.w - __bfloat162float(h3));
    __nv_bfloat162 hp0 = __nv_bfloat162(h0, h1), hp1 = __nv_bfloat162(h2, h3);
    __nv_bfloat162 lp0 = __nv_bfloat162(l0, l1), lp1 = __nv_bfloat162(l2, l3);
    uint2 ho, lo2;
    ho.x = *(uint32_t*)&hp0; ho.y = *(uint32_t*)&hp1;
    lo2.x = *(uint32_t*)&lp0; lo2.y = *(uint32_t*)&lp1;
    hi[i] = ho; lo[i] = lo2;
}

__global__ __launch_bounds__(256)
void wconv_kernel(const float* __restrict__ Wq, const float* __restrict__ Wk,
                  const float* __restrict__ Wv, const float* __restrict__ Wp,
                  unsigned short* __restrict__ wqkv, unsigned short* __restrict__ wp)
{
    int wi = blockIdx.y;
    int n  = blockIdx.x;
    int k  = threadIdx.x;
    const float* W = (wi == 0) ? Wq : (wi == 1) ? Wk : (wi == 2) ? Wv : Wp;
    float val = W[k * 256 + n];
    __nv_bfloat16 h = __float2bfloat16(val);
    __nv_bfloat16 l = __float2bfloat16(val - __bfloat162float(h));
    if (wi < 3) {
        wqkv[(size_t)(wi * 256 + n) * 256 + k]                     = *(unsigned short*)&h;
        wqkv[(size_t)768 * 256 + (size_t)(wi * 256 + n) * 256 + k] = *(unsigned short*)&l;
    } else {
        wp[(size_t)n * 256 + k]                     = *(unsigned short*)&h;
        wp[(size_t)256 * 256 + (size_t)n * 256 + k] = *(unsigned short*)&l;
    }
}

// ---------------- split-bf16 GEMM, 3-stage pipeline, pass-reordered MMAs -----
// C[by*128..+128][bx*128..+128] = A @ B^T (+bias). A hi/lo [M][256], B hi/lo [Ntot][256].
static constexpr int STAGE_BYTES = 32768;
static constexpr int OFF_AH = 0, OFF_AL = 8192, OFF_BH = 16384, OFF_BL = 24576;
static constexpr int GEMM_SMEM = 3 * STAGE_BYTES;

template<bool BIAS>
__global__ __launch_bounds__(256)
void gemm3_kernel(const unsigned short* __restrict__ Ahi, const unsigned short* __restrict__ Alo,
                  const unsigned short* __restrict__ Bhi, const unsigned short* __restrict__ Blo,
                  const float* __restrict__ bias, float* __restrict__ C, int ldc)
{
    extern __shared__ char smem[];
    const uint32_t sb = smem_u32(smem);
    const int tid  = threadIdx.x;
    const int wid  = tid >> 5;
    const int lane = tid & 31;
    const int mw = wid & 1;        // 2 warp rows (64 each)
    const int nw = wid >> 1;       // 4 warp cols (32 each)

    const int mbase = blockIdx.y * 128;
    const int nbase = blockIdx.x * 128;

    auto load_chunk = [&](int kc, int s) {
        const uint32_t stg = sb + s * STAGE_BYTES;
        #pragma unroll
        for (int i = 0; i < 2; i++) {
            int u = tid + i * 256;             // 512 16B-units per 8K tile
            int row = u >> 2, c = u & 3;
            uint32_t so = swz(row, c);
            size_t ga = (size_t)(mbase + row) * 256 + kc * 32 + c * 8;
            size_t gb = (size_t)(nbase + row) * 256 + kc * 32 + c * 8;
            cp_async16(stg + OFF_AH + so, Ahi + ga);
            cp_async16(stg + OFF_AL + so, Alo + ga);
            cp_async16(stg + OFF_BH + so, Bhi + gb);
            cp_async16(stg + OFF_BL + so, Blo + gb);
        }
        cp_commit();
    };

    float acc[4][4][4];
    #pragma unroll
    for (int i = 0; i < 4; i++)
        #pragma unroll
        for (int j = 0; j < 4; j++)
            #pragma unroll
            for (int r = 0; r < 4; r++) acc[i][j][r] = 0.0f;

    load_chunk(0, 0);
    load_chunk(1, 1);

    for (int kc = 0; kc < 8; kc++) {
        if (kc == 7) cp_wait<0>(); else cp_wait<1>();
        __syncthreads();
        if (kc < 6) load_chunk(kc + 2, (kc + 2) % 3);

        const uint32_t stg = sb + (kc % 3) * STAGE_BYTES;
        #pragma unroll
        for (int ks = 0; ks < 2; ks++) {
            uint32_t a_hi[4][4], a_lo[4][4];
            {
                int arow = mw * 64 + (lane & 15);
                int ac   = ks * 2 + (lane >> 4);
                uint32_t base_off = swz(arow, ac);
                #pragma unroll
                for (int mt = 0; mt < 4; mt++) {
                    uint32_t off = base_off + mt * 16 * 64;
                    ldsm4(a_hi[mt], stg + OFF_AH + off);
                    ldsm4(a_lo[mt], stg + OFF_AL + off);
                }
            }
            uint32_t b_hi[4][2], b_lo[4][2];
            {
                int nr0 = nw * 32 + ((lane >> 4) << 3) + (lane & 7);
                int bc  = ks * 2 + ((lane >> 3) & 1);
                #pragma unroll
                for (int nh = 0; nh < 2; nh++) {
                    uint32_t off = swz(nr0 + nh * 16, bc);
                    uint32_t r[4];
                    ldsm4(r, stg + OFF_BH + off);
                    b_hi[nh * 2][0] = r[0]; b_hi[nh * 2][1] = r[1];
                    b_hi[nh * 2 + 1][0] = r[2]; b_hi[nh * 2 + 1][1] = r[3];
                    ldsm4(r, stg + OFF_BL + off);
                    b_lo[nh * 2][0] = r[0]; b_lo[nh * 2][1] = r[1];
                    b_lo[nh * 2 + 1][0] = r[2]; b_lo[nh * 2 + 1][1] = r[3];
                }
            }
            // pass-outermost: consecutive MMAs hit different accumulators
            #pragma unroll
            for (int mt = 0; mt < 4; mt++)
                #pragma unroll
                for (int nt = 0; nt < 4; nt++)
                    mma16816(acc[mt][nt], a_hi[mt], b_hi[nt]);
            #pragma unroll
            for (int mt = 0; mt < 4; mt++)
                #pragma unroll
                for (int nt = 0; nt < 4; nt++)
                    mma16816(acc[mt][nt], a_hi[mt], b_lo[nt]);
            #pragma unroll
            for (int mt = 0; mt < 4; mt++)
                #pragma unroll
                for (int nt = 0; nt < 4; nt++)
                    mma16816(acc[mt][nt], a_lo[mt], b_hi[nt]);
        }
    }

    #pragma unroll
    for (int mt = 0; mt < 4; mt++) {
        int r0 = mbase + mw * 64 + mt * 16 + (lane >> 2);
        #pragma unroll
        for (int nt = 0; nt < 4; nt++) {
            int col = nbase + nw * 32 + nt * 8 + (lane & 3) * 2;
            float b0 = 0.f, b1 = 0.f;
            if (BIAS) { b0 = bias[col]; b1 = bias[col + 1]; }
            *(float2*)(C + (size_t)r0 * ldc + col) =
                make_float2(acc[mt][nt][0] + b0, acc[mt][nt][1] + b1);
            *(float2*)(C + (size_t)(r0 + 8) * ldc + col) =
                make_float2(acc[mt][nt][2] + b0, acc[mt][nt][3] + b1);
        }
    }
}

// ---------------- row-local attention, conflict-free smem --------------------
// 16 rows/CTA, 128 threads = (row r = tid/8, head h = tid%8).
// smem row stride 772 floats (4-bank shift/row); index rotation d=(dd+4h+r)&31
// makes every warp lane hit a distinct bank on q/k/v accesses.
#define QSTR 772
__global__ __launch_bounds__(128)
void attn_kernel(const float* __restrict__ qkv,
                 unsigned short* __restrict__ xhi, unsigned short* __restrict__ xlo)
{
    __shared__ float s[16 * QSTR];
    const int row0 = blockIdx.x * 16;
    const int tid  = threadIdx.x;

    // load 16 rows x 768 floats (3072 float4), smem row stride 193 float4
    const float4* src = (const float4*)(qkv + (size_t)row0 * 768);
    #pragma unroll
    for (int i = 0; i < 24; i++) {
        int u = tid + 128 * i;
        int r = u / 192, c4 = u % 192;
        *((float4*)s + r * 193 + c4) = src[r * 192 + c4];
    }
    __syncthreads();

    const int r = tid >> 3;
    const int h = tid & 7;
    const float* q  = s + r * QSTR + h * 32;
    const float* k  = s + r * QSTR + 256;
    const float* vv = s + r * QSTR + 512;

    const float scale = 0.17677669529663687f;  // 1/sqrt(32)
    const int rot = (4 * h + r) & 31;

    float p[8];
    #pragma unroll
    for (int g = 0; g < 8; g++) p[g] = 0.0f;
    #pragma unroll
    for (int dd = 0; dd < 32; dd++) {
        int d = (dd + rot) & 31;
        float qd = q[d];
        #pragma unroll
        for (int g = 0; g < 8; g++)
            p[g] = fmaf(qd, k[g * 32 + d], p[g]);
    }
    float mx = p[0] * scale;
    #pragma unroll
    for (int g = 1; g < 8; g++) mx = fmaxf(mx, p[g] * scale);
    float sum = 0.0f;
    #pragma unroll
    for (int g = 0; g < 8; g++) { p[g] = __expf(p[g] * scale - mx); sum += p[g]; }
    const float inv = 1.0f / sum;
    #pragma unroll
    for (int g = 0; g < 8; g++) p[g] *= inv;

    float o[32];
    #pragma unroll
    for (int dd = 0; dd < 32; dd++) {
        int d = (dd + rot) & 31;
        float a = 0.0f;
        #pragma unroll
        for (int g = 0; g < 8; g++)
            a = fmaf(p[g], vv[g * 32 + d], a);
        o[d] = a;
    }

    unsigned short hbuf[32], lbuf[32];
    #pragma unroll
    for (int d = 0; d < 32; d++) {
        __nv_bfloat16 hb = __float2bfloat16(o[d]);
        __nv_bfloat16 lb = __float2bfloat16(o[d] - __bfloat162float(hb));
        hbuf[d] = *(unsigned short*)&hb;
        lbuf[d] = *(unsigned short*)&lb;
    }
    size_t base = (size_t)(row0 + r) * 256 + h * 32;
    #pragma unroll
    for (int d = 0; d < 32; d += 8) {
        *(uint4*)(xhi + base + d) = *(uint4*)(hbuf + d);
        *(uint4*)(xlo + base + d) = *(uint4*)(lbuf + d);
    }
}

// ---------------- launch ------------------------------------------------------
extern "C" void kernel_launch(void* const* d_in, const int* in_sizes, int n_in,
                              void* d_out, int out_size)
{
    const float* v  = (const float*)d_in[0];
    const float* Wq = (const float*)d_in[1];
    const float* Wk = (const float*)d_in[2];
    const float* Wv = (const float*)d_in[3];
    const float* Wp = (const float*)d_in[4];
    const float* bp = (const float*)d_in[5];
    float* out = (float*)d_out;

    unsigned short *vhi, *vlo, *xhi, *xlo, *wqkv, *wp;
    float *qkv;
    cudaGetSymbolAddress((void**)&vhi,  g_vhi);
    cudaGetSymbolAddress((void**)&vlo,  g_vlo);
    cudaGetSymbolAddress((void**)&xhi,  g_xhi);
    cudaGetSymbolAddress((void**)&xlo,  g_xlo);
    cudaGetSymbolAddress((void**)&wqkv, g_wqkv);
    cudaGetSymbolAddress((void**)&wp,   g_wp);
    cudaGetSymbolAddress((void**)&qkv,  g_qkv);

    cudaFuncSetAttribute(gemm3_kernel<false>, cudaFuncAttributeMaxDynamicSharedMemorySize, GEMM_SMEM);
    cudaFuncSetAttribute(gemm3_kernel<true>,  cudaFuncAttributeMaxDynamicSharedMemorySize, GEMM_SMEM);

    int n4 = M_TOTAL * DIM / 4;
    split_kernel<<<(n4 + 255) / 256, 256>>>((const float4*)v, (uint2*)vhi, (uint2*)vlo, n4);
    wconv_kernel<<<dim3(256, 4), 256>>>(Wq, Wk, Wv, Wp, wqkv, wp);

    // merged QKV projection: N = 768
    dim3 gq(6, M_TOTAL / 128);
    gemm3_kernel<false><<<gq, 256, GEMM_SMEM>>>(vhi, vlo, wqkv, wqkv + 768 * 256,
                                                nullptr, qkv, 768);
    // attention -> split x
    attn_kernel<<<M_TOTAL / 16, 128>>>(qkv, xhi, xlo);
    // output projection + bias
    dim3 gp(2, M_TOTAL / 128);
    gemm3_kernel<true><<<gp, 256, GEMM_SMEM>>>(xhi, xlo, wp, wp + 256 * 256,
                                               bp, out, DIM);
}

// round 6
// speedup vs baseline: 1.4193x; 1.1424x over previous
#include <cuda_runtime.h>
#include <cuda_bf16.h>
#include <cstdint>

// out = RowLocalAttn(v@Wq, v@Wk, v@Wv) @ Wp + bp
// v: [65536, 256] fp32. GEMMs: warp mma.sync bf16, 3-pass hi/lo split, fp32 accum.
// R6: R5 GEMM path (merged QKV N=768, 3-stage, pass-reordered MMAs) +
// rewritten attention: k|v in padded smem (broadcast/conflict-free), q direct
// from global, all-static register indexing (no spills).

#define M_TOTAL 65536
#define DIM     256

// ---------------- scratch ----------------------------------------------------
__device__ __align__(128) unsigned short g_vhi[(size_t)M_TOTAL * DIM];
__device__ __align__(128) unsigned short g_vlo[(size_t)M_TOTAL * DIM];
__device__ __align__(128) float          g_qkv[(size_t)M_TOTAL * 3 * DIM]; // [M][768]
__device__ __align__(128) unsigned short g_xhi[(size_t)M_TOTAL * DIM];
__device__ __align__(128) unsigned short g_xlo[(size_t)M_TOTAL * DIM];
__device__ __align__(128) unsigned short g_wqkv[2 * 768 * 256];  // hi plane, lo plane ([n][k])
__device__ __align__(128) unsigned short g_wp[2 * 256 * 256];

// ---------------- PTX helpers ------------------------------------------------
__device__ __forceinline__ uint32_t smem_u32(const void* p) {
    uint32_t a;
    asm("{ .reg .u64 t; cvta.to.shared.u64 t, %1; cvt.u32.u64 %0, t; }" : "=r"(a) : "l"(p));
    return a;
}
__device__ __forceinline__ void cp_async16(uint32_t s, const void* g) {
    asm volatile("cp.async.cg.shared.global [%0], [%1], 16;" :: "r"(s), "l"(g));
}
__device__ __forceinline__ void cp_commit() { asm volatile("cp.async.commit_group;"); }
template<int N>
__device__ __forceinline__ void cp_wait() { asm volatile("cp.async.wait_group %0;" :: "n"(N)); }
__device__ __forceinline__ void ldsm4(uint32_t* r, uint32_t a) {
    asm volatile("ldmatrix.sync.aligned.m8n8.x4.shared.b16 {%0,%1,%2,%3}, [%4];"
        : "=r"(r[0]), "=r"(r[1]), "=r"(r[2]), "=r"(r[3]) : "r"(a));
}
__device__ __forceinline__ void mma16816(float* d, const uint32_t* a, const uint32_t* b) {
    asm volatile("mma.sync.aligned.m16n8k16.row.col.f32.bf16.bf16.f32 "
        "{%0,%1,%2,%3}, {%4,%5,%6,%7}, {%8,%9}, {%0,%1,%2,%3};"
        : "+f"(d[0]), "+f"(d[1]), "+f"(d[2]), "+f"(d[3])
        : "r"(a[0]), "r"(a[1]), "r"(a[2]), "r"(a[3]), "r"(b[0]), "r"(b[1]));
}
// swizzled offset in an N-row x 64-byte tile (16B granules)
__device__ __forceinline__ uint32_t swz(int row, int c) {
    return (uint32_t)(row * 64 + ((c ^ ((row >> 1) & 3)) << 4));
}

// ---------------- conversion kernels ----------------------------------------
__global__ __launch_bounds__(256)
void split_kernel(const float4* __restrict__ in, uint2* __restrict__ hi,
                  uint2* __restrict__ lo, int n4)
{
    int i = blockIdx.x * blockDim.x + threadIdx.x;
    if (i >= n4) return;
    float4 f = in[i];
    __nv_bfloat16 h0 = __float2bfloat16(f.x);
    __nv_bfloat16 h1 = __float2bfloat16(f.y);
    __nv_bfloat16 h2 = __float2bfloat16(f.z);
    __nv_bfloat16 h3 = __float2bfloat16(f.w);
    __nv_bfloat16 l0 = __float2bfloat16(f.x - __bfloat162float(h0));
    __nv_bfloat16 l1 = __float2bfloat16(f.y - __bfloat162float(h1));
    __nv_bfloat16 l2 = __float2bfloat16(f.z - __bfloat162float(h2));
    __nv_bfloat16 l3 = __float2bfloat16(f.w - __bfloat162float(h3));
    __nv_bfloat162 hp0 = __nv_bfloat162(h0, h1), hp1 = __nv_bfloat162(h2, h3);
    __nv_bfloat162 lp0 = __nv_bfloat162(l0, l1), lp1 = __nv_bfloat162(l2, l3);
    uint2 ho, lo2;
    ho.x = *(uint32_t*)&hp0; ho.y = *(uint32_t*)&hp1;
    lo2.x = *(uint32_t*)&lp0; lo2.y = *(uint32_t*)&lp1;
    hi[i] = ho; lo[i] = lo2;
}

__global__ __launch_bounds__(256)
void wconv_kernel(const float* __restrict__ Wq, const float* __restrict__ Wk,
                  const float* __restrict__ Wv, const float* __restrict__ Wp,
                  unsigned short* __restrict__ wqkv, unsigned short* __restrict__ wp)
{
    int wi = blockIdx.y;
    int n  = blockIdx.x;
    int k  = threadIdx.x;
    const float* W = (wi == 0) ? Wq : (wi == 1) ? Wk : (wi == 2) ? Wv : Wp;
    float val = W[k * 256 + n];
    __nv_bfloat16 h = __float2bfloat16(val);
    __nv_bfloat16 l = __float2bfloat16(val - __bfloat162float(h));
    if (wi < 3) {
        wqkv[(size_t)(wi * 256 + n) * 256 + k]                     = *(unsigned short*)&h;
        wqkv[(size_t)768 * 256 + (size_t)(wi * 256 + n) * 256 + k] = *(unsigned short*)&l;
    } else {
        wp[(size_t)n * 256 + k]                     = *(unsigned short*)&h;
        wp[(size_t)256 * 256 + (size_t)n * 256 + k] = *(unsigned short*)&l;
    }
}

// ---------------- split-bf16 GEMM, 3-stage pipeline, pass-reordered MMAs -----
static constexpr int STAGE_BYTES = 32768;
static constexpr int OFF_AH = 0, OFF_AL = 8192, OFF_BH = 16384, OFF_BL = 24576;
static constexpr int GEMM_SMEM = 3 * STAGE_BYTES;

template<bool BIAS>
__global__ __launch_bounds__(256)
void gemm3_kernel(const unsigned short* __restrict__ Ahi, const unsigned short* __restrict__ Alo,
                  const unsigned short* __restrict__ Bhi, const unsigned short* __restrict__ Blo,
                  const float* __restrict__ bias, float* __restrict__ C, int ldc)
{
    extern __shared__ char smem[];
    const uint32_t sb = smem_u32(smem);
    const int tid  = threadIdx.x;
    const int wid  = tid >> 5;
    const int lane = tid & 31;
    const int mw = wid & 1;        // 2 warp rows (64 each)
    const int nw = wid >> 1;       // 4 warp cols (32 each)

    const int mbase = blockIdx.y * 128;
    const int nbase = blockIdx.x * 128;

    auto load_chunk = [&](int kc, int s) {
        const uint32_t stg = sb + s * STAGE_BYTES;
        #pragma unroll
        for (int i = 0; i < 2; i++) {
            int u = tid + i * 256;             // 512 16B-units per 8K tile
            int row = u >> 2, c = u & 3;
            uint32_t so = swz(row, c);
            size_t ga = (size_t)(mbase + row) * 256 + kc * 32 + c * 8;
            size_t gb = (size_t)(nbase + row) * 256 + kc * 32 + c * 8;
            cp_async16(stg + OFF_AH + so, Ahi + ga);
            cp_async16(stg + OFF_AL + so, Alo + ga);
            cp_async16(stg + OFF_BH + so, Bhi + gb);
            cp_async16(stg + OFF_BL + so, Blo + gb);
        }
        cp_commit();
    };

    float acc[4][4][4];
    #pragma unroll
    for (int i = 0; i < 4; i++)
        #pragma unroll
        for (int j = 0; j < 4; j++)
            #pragma unroll
            for (int r = 0; r < 4; r++) acc[i][j][r] = 0.0f;

    load_chunk(0, 0);
    load_chunk(1, 1);

    for (int kc = 0; kc < 8; kc++) {
        if (kc == 7) cp_wait<0>(); else cp_wait<1>();
        __syncthreads();
        if (kc < 6) load_chunk(kc + 2, (kc + 2) % 3);

        const uint32_t stg = sb + (kc % 3) * STAGE_BYTES;
        #pragma unroll
        for (int ks = 0; ks < 2; ks++) {
            uint32_t a_hi[4][4], a_lo[4][4];
            {
                int arow = mw * 64 + (lane & 15);
                int ac   = ks * 2 + (lane >> 4);
                uint32_t base_off = swz(arow, ac);
                #pragma unroll
                for (int mt = 0; mt < 4; mt++) {
                    uint32_t off = base_off + mt * 16 * 64;
                    ldsm4(a_hi[mt], stg + OFF_AH + off);
                    ldsm4(a_lo[mt], stg + OFF_AL + off);
                }
            }
            uint32_t b_hi[4][2], b_lo[4][2];
            {
                int nr0 = nw * 32 + ((lane >> 4) << 3) + (lane & 7);
                int bc  = ks * 2 + ((lane >> 3) & 1);
                #pragma unroll
                for (int nh = 0; nh < 2; nh++) {
                    uint32_t off = swz(nr0 + nh * 16, bc);
                    uint32_t r[4];
                    ldsm4(r, stg + OFF_BH + off);
                    b_hi[nh * 2][0] = r[0]; b_hi[nh * 2][1] = r[1];
                    b_hi[nh * 2 + 1][0] = r[2]; b_hi[nh * 2 + 1][1] = r[3];
                    ldsm4(r, stg + OFF_BL + off);
                    b_lo[nh * 2][0] = r[0]; b_lo[nh * 2][1] = r[1];
                    b_lo[nh * 2 + 1][0] = r[2]; b_lo[nh * 2 + 1][1] = r[3];
                }
            }
            // pass-outermost: consecutive MMAs hit different accumulators
            #pragma unroll
            for (int mt = 0; mt < 4; mt++)
                #pragma unroll
                for (int nt = 0; nt < 4; nt++)
                    mma16816(acc[mt][nt], a_hi[mt], b_hi[nt]);
            #pragma unroll
            for (int mt = 0; mt < 4; mt++)
                #pragma unroll
                for (int nt = 0; nt < 4; nt++)
                    mma16816(acc[mt][nt], a_hi[mt], b_lo[nt]);
            #pragma unroll
            for (int mt = 0; mt < 4; mt++)
                #pragma unroll
                for (int nt = 0; nt < 4; nt++)
                    mma16816(acc[mt][nt], a_lo[mt], b_hi[nt]);
        }
    }

    #pragma unroll
    for (int mt = 0; mt < 4; mt++) {
        int r0 = mbase + mw * 64 + mt * 16 + (lane >> 2);
        #pragma unroll
        for (int nt = 0; nt < 4; nt++) {
            int col = nbase + nw * 32 + nt * 8 + (lane & 3) * 2;
            float b0 = 0.f, b1 = 0.f;
            if (BIAS) { b0 = bias[col]; b1 = bias[col + 1]; }
            *(float2*)(C + (size_t)r0 * ldc + col) =
                make_float2(acc[mt][nt][0] + b0, acc[mt][nt][1] + b1);
            *(float2*)(C + (size_t)(r0 + 8) * ldc + col) =
                make_float2(acc[mt][nt][2] + b0, acc[mt][nt][3] + b1);
        }
    }
}

// ---------------- row-local attention ----------------------------------------
// 32 rows/CTA, 256 threads = (row r = tid/8, head h = tid%8).
// Only k|v staged in smem (512 floats/row, padded to 516 -> rows land on
// distinct banks; identical addresses across heads broadcast). q loaded
// directly from global (coalesced 128B per row across 8 heads).
// All register arrays statically indexed -> no local-memory spills.
#define KVSTR 516
__global__ __launch_bounds__(256, 3)
void attn_kernel(const float* __restrict__ qkv,
                 unsigned short* __restrict__ xhi, unsigned short* __restrict__ xlo)
{
    __shared__ float s[32 * KVSTR];
    const int row0 = blockIdx.x * 32;
    const int tid  = threadIdx.x;

    // stage k|v: 32 rows x 512 floats = 4096 float4, 16 per thread
    const float4* src = (const float4*)qkv;
    #pragma unroll
    for (int i = 0; i < 16; i++) {
        int u = tid + 256 * i;
        int r = u >> 7, c4 = u & 127;        // 128 float4 per row
        *((float4*)s + r * 129 + c4) = src[(size_t)(row0 + r) * 192 + 64 + c4];
    }
    __syncthreads();

    const int r = tid >> 3;
    const int h = tid & 7;
    const float* k  = s + r * KVSTR;
    const float* vv = s + r * KVSTR + 256;

    // q: this thread's 32 values, direct from global (8 float4, coalesced)
    float q[32];
    {
        const float4* qsrc = (const float4*)(qkv + (size_t)(row0 + r) * 768 + h * 32);
        #pragma unroll
        for (int i = 0; i < 8; i++) {
            float4 f = qsrc[i];
            q[i * 4 + 0] = f.x; q[i * 4 + 1] = f.y;
            q[i * 4 + 2] = f.z; q[i * 4 + 3] = f.w;
        }
    }

    const float scale = 0.17677669529663687f;  // 1/sqrt(32)

    float p[8];
    #pragma unroll
    for (int g = 0; g < 8; g++) p[g] = 0.0f;
    #pragma unroll
    for (int d = 0; d < 32; d++) {
        float qd = q[d];
        #pragma unroll
        for (int g = 0; g < 8; g++)
            p[g] = fmaf(qd, k[g * 32 + d], p[g]);
    }
    float mx = p[0] * scale;
    #pragma unroll
    for (int g = 1; g < 8; g++) mx = fmaxf(mx, p[g] * scale);
    float sum = 0.0f;
    #pragma unroll
    for (int g = 0; g < 8; g++) { p[g] = __expf(p[g] * scale - mx); sum += p[g]; }
    const float inv = 1.0f / sum;
    #pragma unroll
    for (int g = 0; g < 8; g++) p[g] *= inv;

    // AV + split-store in chunks of 8 (keeps live registers low)
    size_t base = (size_t)(row0 + r) * 256 + h * 32;
    #pragma unroll
    for (int cb = 0; cb < 4; cb++) {
        unsigned short hbuf[8], lbuf[8];
        #pragma unroll
        for (int dd = 0; dd < 8; dd++) {
            int d = cb * 8 + dd;
            float a = 0.0f;
            #pragma unroll
            for (int g = 0; g < 8; g++)
                a = fmaf(p[g], vv[g * 32 + d], a);
            __nv_bfloat16 hb = __float2bfloat16(a);
            __nv_bfloat16 lb = __float2bfloat16(a - __bfloat162float(hb));
            hbuf[dd] = *(unsigned short*)&hb;
            lbuf[dd] = *(unsigned short*)&lb;
        }
        *(uint4*)(xhi + base + cb * 8) = *(uint4*)hbuf;
        *(uint4*)(xlo + base + cb * 8) = *(uint4*)lbuf;
    }
}

// ---------------- launch ------------------------------------------------------
extern "C" void kernel_launch(void* const* d_in, const int* in_sizes, int n_in,
                              void* d_out, int out_size)
{
    const float* v  = (const float*)d_in[0];
    const float* Wq = (const float*)d_in[1];
    const float* Wk = (const float*)d_in[2];
    const float* Wv = (const float*)d_in[3];
    const float* Wp = (const float*)d_in[4];
    const float* bp = (const float*)d_in[5];
    float* out = (float*)d_out;

    unsigned short *vhi, *vlo, *xhi, *xlo, *wqkv, *wp;
    float *qkv;
    cudaGetSymbolAddress((void**)&vhi,  g_vhi);
    cudaGetSymbolAddress((void**)&vlo,  g_vlo);
    cudaGetSymbolAddress((void**)&xhi,  g_xhi);
    cudaGetSymbolAddress((void**)&xlo,  g_xlo);
    cudaGetSymbolAddress((void**)&wqkv, g_wqkv);
    cudaGetSymbolAddress((void**)&wp,   g_wp);
    cudaGetSymbolAddress((void**)&qkv,  g_qkv);

    cudaFuncSetAttribute(gemm3_kernel<false>, cudaFuncAttributeMaxDynamicSharedMemorySize, GEMM_SMEM);
    cudaFuncSetAttribute(gemm3_kernel<true>,  cudaFuncAttributeMaxDynamicSharedMemorySize, GEMM_SMEM);

    int n4 = M_TOTAL * DIM / 4;
    split_kernel<<<(n4 + 255) / 256, 256>>>((const float4*)v, (uint2*)vhi, (uint2*)vlo, n4);
    wconv_kernel<<<dim3(256, 4), 256>>>(Wq, Wk, Wv, Wp, wqkv, wp);

    // merged QKV projection: N = 768
    dim3 gq(6, M_TOTAL / 128);
    gemm3_kernel<false><<<gq, 256, GEMM_SMEM>>>(vhi, vlo, wqkv, wqkv + 768 * 256,
                                                nullptr, qkv, 768);
    // attention -> split x
    attn_kernel<<<M_TOTAL / 32, 256>>>(qkv, xhi, xlo);
    // output projection + bias
    dim3 gp(2, M_TOTAL / 128);
    gemm3_kernel<true><<<gp, 256, GEMM_SMEM>>>(xhi, xlo, wp, wp + 256 * 256,
                                               bp, out, DIM);
}